// round 11
// baseline (speedup 1.0000x reference)
#include <cuda_runtime.h>

// SparseAudioModel gather:
//   out[b, s] = sum_e x[b, e, s - time_e],  time_e = idx[b,e]*256, active iff time_e <= s
//
// R11 = R10 (WIN: 10.94us, float4 + held 80-reg batch) with coarser per-block
// stream granularity: one contiguous 1024-sample tile per block (4KB touched
// per event stream, contiguous) instead of two distant 512-sample tiles.
// Each thread: two float4 groups 512 samples apart inside the tile.
// Same proven schedule: GRP=8 events x 2 = 16 predicated LDG.128 batched
// before any FADD; __launch_bounds__(128, 6) keeps the batch in registers.
// 512 co-resident blocks; predicates uniform (times are multiples of 256).

#define N_SAMPLES 32768
#define N_EVENTS  64
#define STEP_SIZE 256
#define BATCH     16
#define TILE      1024                // one tile = 128 threads * 8 samples
#define NTILES    (N_SAMPLES / TILE)  // 32
#define HALF      512                 // second float4 group offset (samples)
#define GRP       8

__global__ __launch_bounds__(128, 6) void sparse_audio_gather(
    const float* __restrict__ x,      // [B, E, S]
    const int*   __restrict__ idx,    // [B, E]
    float*       __restrict__ out)    // [B, S]
{
    __shared__ int s_time[N_EVENTS];

    const int k = blockIdx.x;         // tile id 0..31
    const int b = blockIdx.y;
    const int t = threadIdx.x;

    if (t < N_EVENTS)
        s_time[t] = idx[b * N_EVENTS + t] * STEP_SIZE;
    __syncthreads();

    const int s_a = k * TILE + t * 4;         // first float4 group
    const int s_b = s_a + HALF;               // second float4 group (+2KB)

    const float* xb = x + (size_t)b * N_EVENTS * N_SAMPLES;

    float4 aa = make_float4(0.f, 0.f, 0.f, 0.f);
    float4 ab = make_float4(0.f, 0.f, 0.f, 0.f);

    #pragma unroll
    for (int g = 0; g < N_EVENTS; g += GRP) {
        float4 va[GRP], vb[GRP];

        // ---- issue 16 predicated LDG.128, no consumption yet ----
        #pragma unroll
        for (int j = 0; j < GRP; ++j) {
            const int e    = g + j;
            const int time = s_time[e];
            const float* pe = xb + (size_t)e * N_SAMPLES - time;

            va[j] = make_float4(0.f, 0.f, 0.f, 0.f);
            vb[j] = make_float4(0.f, 0.f, 0.f, 0.f);

            asm("{\n\t"
                ".reg .pred p;\n\t"
                "setp.le.s32 p, %4, %5;\n\t"
                "@p ld.global.cs.v4.f32 {%0, %1, %2, %3}, [%6];\n\t"
                "}"
                : "+f"(va[j].x), "+f"(va[j].y), "+f"(va[j].z), "+f"(va[j].w)
                : "r"(time), "r"(s_a), "l"(pe + s_a));

            asm("{\n\t"
                ".reg .pred p;\n\t"
                "setp.le.s32 p, %4, %5;\n\t"
                "@p ld.global.cs.v4.f32 {%0, %1, %2, %3}, [%6];\n\t"
                "}"
                : "+f"(vb[j].x), "+f"(vb[j].y), "+f"(vb[j].z), "+f"(vb[j].w)
                : "r"(time), "r"(s_b), "l"(pe + s_b));
        }

        // ---- consume ----
        #pragma unroll
        for (int j = 0; j < GRP; ++j) {
            aa.x += va[j].x; aa.y += va[j].y; aa.z += va[j].z; aa.w += va[j].w;
            ab.x += vb[j].x; ab.y += vb[j].y; ab.z += vb[j].z; ab.w += vb[j].w;
        }
    }

    float* ob = out + (size_t)b * N_SAMPLES;
    asm("st.global.cs.v4.f32 [%0], {%1, %2, %3, %4};"
        :: "l"(ob + s_a), "f"(aa.x), "f"(aa.y), "f"(aa.z), "f"(aa.w) : "memory");
    asm("st.global.cs.v4.f32 [%0], {%1, %2, %3, %4};"
        :: "l"(ob + s_b), "f"(ab.x), "f"(ab.y), "f"(ab.z), "f"(ab.w) : "memory");
}

extern "C" void kernel_launch(void* const* d_in, const int* in_sizes, int n_in,
                              void* d_out, int out_size)
{
    const float* x   = (const float*)d_in[0];   // [16, 64, 32768] float32
    const int*   idx = (const int*)  d_in[1];   // [16, 64] int32
    float*       out = (float*)d_out;           // [16, 1, 32768] float32

    dim3 block(128);
    dim3 grid(NTILES, BATCH);                   // (32, 16) = 512 blocks
    sparse_audio_gather<<<grid, block>>>(x, idx, out);
}

// round 12
// speedup vs baseline: 1.0896x; 1.0896x over previous
#include <cuda_runtime.h>

// SparseAudioModel gather:
//   out[b, s] = sum_e x[b, e, s - time_e],  time_e = idx[b,e]*256, active iff time_e <= s
//
// R12 = R10 (WIN: 10.94us) with 4x finer work units to kill the wave-
// quantization tail: 64-thread blocks, 256-sample tiles, mirror pairs
// (k, 127-k) -> 1024 uniform blocks = 6.92/SM (+1.2% quantization) instead of
// R10's 512 blocks = 3.46/SM (68 SMs carry +15.6%).
// Unchanged proven ingredients: LDG.128 (512B warp requests), GRP=8 x 2 = 16
// predicated loads held in an 80-reg batch, .cs streaming, uniform blocks.

#define N_SAMPLES 32768
#define N_EVENTS  64
#define STEP_SIZE 256
#define BATCH     16
#define TILE      256                 // one tile = 64 threads * float4
#define NTILES    (N_SAMPLES / TILE)  // 128
#define GRP       8

__global__ __launch_bounds__(64, 12) void sparse_audio_gather(
    const float* __restrict__ x,      // [B, E, S]
    const int*   __restrict__ idx,    // [B, E]
    float*       __restrict__ out)    // [B, S]
{
    __shared__ int s_time[N_EVENTS];

    const int k = blockIdx.x;         // tile pair id 0..63
    const int b = blockIdx.y;
    const int t = threadIdx.x;

    s_time[t] = idx[b * N_EVENTS + t] * STEP_SIZE;   // 64 threads, 64 events
    __syncthreads();

    const int s_lo = k * TILE + t * 4;                 // light tile
    const int s_hi = (NTILES - 1 - k) * TILE + t * 4;  // heavy tile

    const float* xb = x + (size_t)b * N_EVENTS * N_SAMPLES;

    float4 al = make_float4(0.f, 0.f, 0.f, 0.f);
    float4 ah = make_float4(0.f, 0.f, 0.f, 0.f);

    #pragma unroll
    for (int g = 0; g < N_EVENTS; g += GRP) {
        float4 vl[GRP], vh[GRP];

        // ---- issue 16 predicated LDG.128, no consumption yet ----
        #pragma unroll
        for (int j = 0; j < GRP; ++j) {
            const int e    = g + j;
            const int time = s_time[e];
            const float* pe = xb + (size_t)e * N_SAMPLES - time;

            vl[j] = make_float4(0.f, 0.f, 0.f, 0.f);
            vh[j] = make_float4(0.f, 0.f, 0.f, 0.f);

            asm("{\n\t"
                ".reg .pred p;\n\t"
                "setp.le.s32 p, %4, %5;\n\t"
                "@p ld.global.cs.v4.f32 {%0, %1, %2, %3}, [%6];\n\t"
                "}"
                : "+f"(vl[j].x), "+f"(vl[j].y), "+f"(vl[j].z), "+f"(vl[j].w)
                : "r"(time), "r"(s_lo), "l"(pe + s_lo));

            asm("{\n\t"
                ".reg .pred p;\n\t"
                "setp.le.s32 p, %4, %5;\n\t"
                "@p ld.global.cs.v4.f32 {%0, %1, %2, %3}, [%6];\n\t"
                "}"
                : "+f"(vh[j].x), "+f"(vh[j].y), "+f"(vh[j].z), "+f"(vh[j].w)
                : "r"(time), "r"(s_hi), "l"(pe + s_hi));
        }

        // ---- consume ----
        #pragma unroll
        for (int j = 0; j < GRP; ++j) {
            al.x += vl[j].x; al.y += vl[j].y; al.z += vl[j].z; al.w += vl[j].w;
            ah.x += vh[j].x; ah.y += vh[j].y; ah.z += vh[j].z; ah.w += vh[j].w;
        }
    }

    float* ob = out + (size_t)b * N_SAMPLES;
    asm("st.global.cs.v4.f32 [%0], {%1, %2, %3, %4};"
        :: "l"(ob + s_lo), "f"(al.x), "f"(al.y), "f"(al.z), "f"(al.w) : "memory");
    asm("st.global.cs.v4.f32 [%0], {%1, %2, %3, %4};"
        :: "l"(ob + s_hi), "f"(ah.x), "f"(ah.y), "f"(ah.z), "f"(ah.w) : "memory");
}

extern "C" void kernel_launch(void* const* d_in, const int* in_sizes, int n_in,
                              void* d_out, int out_size)
{
    const float* x   = (const float*)d_in[0];   // [16, 64, 32768] float32
    const int*   idx = (const int*)  d_in[1];   // [16, 64] int32
    float*       out = (float*)d_out;           // [16, 1, 32768] float32

    dim3 block(64);
    dim3 grid(NTILES / 2, BATCH);               // (64, 16) = 1024 blocks
    sparse_audio_gather<<<grid, block>>>(x, idx, out);
}